// round 1
// baseline (speedup 1.0000x reference)
#include <cuda_runtime.h>

#define NB   8
#define NS   2048
#define NH   256
#define NHH  128
#define NP   64
#define NQG  20
#define NTOK (NB*NS)

// ---- scratch (device globals; no allocation allowed) ----
__device__ float g_sim[NTOK];          // sim logits, then overwritten with exp(sim - M)
__device__ float g_conf[NTOK];         // sigmoid(conf logit)
__device__ float g_M[NB*NQG];          // per-group softmax max (clamped with 0)
__device__ float g_Z[NB*NQG];          // in-group sum of exp
__device__ float g_cnt[NB*NQG];        // group count
__device__ float g_W[NB*NQG*NP];       // in-group exp-weighted param sums
__device__ float g_T[NB*NQG*NP];       // in-group plain param sums
__device__ float g_V[NB*NQG*NP];       // final per-group smoothed vectors

// ================= K0: zero accumulators =================
__global__ void k_zero() {
    int i = blockIdx.x * blockDim.x + threadIdx.x;
    if (i < NB*NQG*NP) { g_W[i] = 0.f; g_T[i] = 0.f; }
}

// ================= K1: fused dual-MLP (sim + conf logits) =================
// GEMM [16384,256] x [256,256] (cols 0..127 = sim hidden, 128..255 = conf hidden),
// fused ReLU + second-layer reduction -> per-token sim logit / conf sigmoid.
__global__ __launch_bounds__(256, 2) void k_mlp(
    const float* __restrict__ x,
    const float* __restrict__ sw1, const float* __restrict__ sb1,
    const float* __restrict__ sw2, const float* __restrict__ sb2,
    const float* __restrict__ cw1, const float* __restrict__ cb1,
    const float* __restrict__ cw2, const float* __restrict__ cb2)
{
    __shared__ __align__(16) float Xs[64][36];   // 64 tokens x 32 k (+pad)
    __shared__ __align__(16) float Ws[32][256];  // 32 k x 256 hidden

    const int tid = threadIdx.x;
    const int tx  = tid & 31;       // hidden-col group: owns cols tx*8 .. tx*8+7
    const int ty  = tid >> 5;       // token group: owns rows ty*8 .. ty*8+7
    const int ty8 = ty * 8;
    const int tx8 = tx * 8;
    const int row0 = blockIdx.x * 64;

    float acc[8][8];
    #pragma unroll
    for (int i = 0; i < 8; ++i)
        #pragma unroll
        for (int j = 0; j < 8; ++j) acc[i][j] = 0.f;

    // preload layer-2 params for this thread's 8 hidden columns
    float b1v[8], w2v[8], b2v;
    if (tx < 16) {
        const int c0 = tx8;
        #pragma unroll
        for (int j = 0; j < 8; ++j) { b1v[j] = sb1[c0+j]; w2v[j] = sw2[c0+j]; }
        b2v = sb2[0];
    } else {
        const int c0 = tx8 - 128;
        #pragma unroll
        for (int j = 0; j < 8; ++j) { b1v[j] = cb1[c0+j]; w2v[j] = cw2[c0+j]; }
        b2v = cb2[0];
    }

    for (int kb = 0; kb < NH; kb += 32) {
        // X tile: 64 tokens x 32 k = 512 float4
        #pragma unroll
        for (int i = tid; i < 512; i += 256) {
            int t = i >> 3, j = i & 7;
            float4 v = *(const float4*)&x[(size_t)(row0 + t) * NH + kb + j * 4];
            *(float4*)&Xs[t][j * 4] = v;
        }
        // W tile: 32 k x 256 hidden = 2048 float4 (sim cols | conf cols)
        #pragma unroll
        for (int i = tid; i < 2048; i += 256) {
            int kk = i >> 6, f4 = i & 63;
            int c0 = f4 * 4;
            const float* src = (c0 < 128) ? &sw1[(size_t)(kb + kk) * NHH + c0]
                                          : &cw1[(size_t)(kb + kk) * NHH + c0 - 128];
            *(float4*)&Ws[kk][c0] = *(const float4*)src;
        }
        __syncthreads();

        #pragma unroll 4
        for (int kk = 0; kk < 32; ++kk) {
            float xv[8];
            #pragma unroll
            for (int i = 0; i < 8; ++i) xv[i] = Xs[ty8 + i][kk];   // warp-broadcast
            float4 wa = *(const float4*)&Ws[kk][tx8];
            float4 wb = *(const float4*)&Ws[kk][tx8 + 4];
            float wv[8] = {wa.x, wa.y, wa.z, wa.w, wb.x, wb.y, wb.z, wb.w};
            #pragma unroll
            for (int i = 0; i < 8; ++i)
                #pragma unroll
                for (int j = 0; j < 8; ++j)
                    acc[i][j] = fmaf(xv[i], wv[j], acc[i][j]);
        }
        __syncthreads();
    }

    // layer 2: bias + relu + dot with w2 over this thread's 8 columns
    float part[8];
    #pragma unroll
    for (int i = 0; i < 8; ++i) {
        float s = 0.f;
        #pragma unroll
        for (int j = 0; j < 8; ++j) {
            float h = fmaxf(acc[i][j] + b1v[j], 0.f);
            s = fmaf(h, w2v[j], s);
        }
        part[i] = s;
    }
    // butterfly reduce within each 16-lane half (lanes 0-15: sim, 16-31: conf)
    #pragma unroll
    for (int off = 8; off >= 1; off >>= 1)
        #pragma unroll
        for (int i = 0; i < 8; ++i)
            part[i] += __shfl_xor_sync(0xffffffffu, part[i], off);

    if (tx == 0) {
        #pragma unroll
        for (int i = 0; i < 8; ++i) g_sim[row0 + ty8 + i] = part[i] + b2v;
    }
    if (tx == 16) {
        #pragma unroll
        for (int i = 0; i < 8; ++i) {
            float l = part[i] + b2v;
            g_conf[row0 + ty8 + i] = 1.f / (1.f + __expf(-l));
        }
    }
}

// ================= K2: per-(batch,group) max / Z / count; write e = exp(sim-M) =================
__global__ void k_stats(const int* __restrict__ questions) {
    const int b = blockIdx.x;
    const int tid = threadIdx.x;          // 256
    __shared__ unsigned menc[NQG];
    __shared__ float Msh[NQG], Zsh[NQG];
    __shared__ int   csh[NQG];
    if (tid < NQG) { menc[tid] = 0u; Zsh[tid] = 0.f; csh[tid] = 0; }
    __syncthreads();
    const int base = b * NS;
    for (int s = tid; s < NS; s += 256) {
        float v = g_sim[base + s];
        unsigned bits = __float_as_uint(v);
        unsigned enc = (bits & 0x80000000u) ? ~bits : (bits | 0x80000000u); // order-preserving
        atomicMax(&menc[questions[base + s]], enc);
    }
    __syncthreads();
    if (tid < NQG) {
        unsigned e = menc[tid];
        float gm = -3.4e38f;
        if (e) gm = (e & 0x80000000u) ? __uint_as_float(e & 0x7fffffffu)
                                      : __uint_as_float(~e);
        float M = fmaxf(gm, 0.f);   // out-group logits are 0 and participate in softmax
        Msh[tid] = M;
        g_M[b * NQG + tid] = M;
    }
    __syncthreads();
    for (int s = tid; s < NS; s += 256) {
        int q = questions[base + s];
        float e = __expf(g_sim[base + s] - Msh[q]);
        g_sim[base + s] = e;                 // overwrite own slot with exp term
        atomicAdd(&Zsh[q], e);
        atomicAdd(&csh[q], 1);
    }
    __syncthreads();
    if (tid < NQG) {
        g_Z[b * NQG + tid]   = Zsh[tid];
        g_cnt[b * NQG + tid] = (float)csh[tid];
    }
}

// ================= K3: per-group weighted sums of param_x =================
// grid = NB*32 blocks (64 tokens each), 64 threads = one per p column.
__global__ __launch_bounds__(64) void k_accum(const float* __restrict__ px,
                                              const int* __restrict__ questions) {
    const int b     = blockIdx.x >> 5;
    const int chunk = blockIdx.x & 31;
    const int t0    = b * NS + chunk * 64;
    const int p     = threadIdx.x;
    __shared__ float accW[NQG][NP];
    __shared__ float accT[NQG][NP];
    __shared__ float esh[64];
    __shared__ int   qsh[64];
    #pragma unroll
    for (int g = 0; g < NQG; ++g) { accW[g][p] = 0.f; accT[g][p] = 0.f; }
    esh[p] = g_sim[t0 + p];       // e terms
    qsh[p] = questions[t0 + p];
    __syncthreads();

    for (int c = 0; c < 64; c += 8) {
        float pxv[8];
        #pragma unroll
        for (int u = 0; u < 8; ++u)
            pxv[u] = px[(size_t)(t0 + c + u) * NP + p];   // 8 independent loads (MLP=8)
        #pragma unroll
        for (int u = 0; u < 8; ++u) {
            int g = qsh[c + u];
            accW[g][p] = fmaf(esh[c + u], pxv[u], accW[g][p]);
            accT[g][p] += pxv[u];
        }
    }
    const int bg = b * NQG;
    for (int g = 0; g < NQG; ++g) {
        atomicAdd(&g_W[(bg + g) * NP + p], accW[g][p]);
        atomicAdd(&g_T[(bg + g) * NP + p], accT[g][p]);
    }
}

// ================= K4: finalize V_g =================
__global__ void k_finalize() {
    const int b = blockIdx.x;
    const int p = threadIdx.x;   // 64
    const int bg = b * NQG;
    float tall = 0.f;
    for (int g = 0; g < NQG; ++g) tall += g_T[(bg + g) * NP + p];
    for (int g = 0; g < NQG; ++g) {
        float M  = g_M[bg + g];
        float em = __expf(-M);
        float Tg = g_T[(bg + g) * NP + p];
        float Z  = g_Z[bg + g] + ((float)NS - g_cnt[bg + g]) * em;
        g_V[(bg + g) * NP + p] = (g_W[(bg + g) * NP + p] + em * (tall - Tg)) / Z;
    }
}

// ================= K5: output blend =================
__global__ void k_out(const float* __restrict__ px, const int* __restrict__ questions,
                      float* __restrict__ out) {
    int fid = blockIdx.x * blockDim.x + threadIdx.x;   // over 262144 float4
    int t  = fid >> 4;          // 16 float4 per token
    int pq = fid & 15;
    int b  = t >> 11;
    int q  = questions[t];
    float c = g_conf[t];
    float4 pv = *(const float4*)&px[(size_t)t * NP + pq * 4];
    float4 vv = *(const float4*)&g_V[((b * NQG) + q) * NP + pq * 4];
    float4 o;
    float ic = 1.f - c;
    o.x = fmaf(c, pv.x, ic * vv.x);
    o.y = fmaf(c, pv.y, ic * vv.y);
    o.z = fmaf(c, pv.z, ic * vv.z);
    o.w = fmaf(c, pv.w, ic * vv.w);
    *(float4*)&out[(size_t)t * NP + pq * 4] = o;
}

extern "C" void kernel_launch(void* const* d_in, const int* in_sizes, int n_in,
                              void* d_out, int out_size) {
    const float* x   = (const float*)d_in[0];
    const float* px  = (const float*)d_in[1];
    const float* sw1 = (const float*)d_in[2];
    const float* sb1 = (const float*)d_in[3];
    const float* sw2 = (const float*)d_in[4];
    const float* sb2 = (const float*)d_in[5];
    const float* cw1 = (const float*)d_in[6];
    const float* cb1 = (const float*)d_in[7];
    const float* cw2 = (const float*)d_in[8];
    const float* cb2 = (const float*)d_in[9];
    const int*   qs  = (const int*)d_in[10];
    float* out = (float*)d_out;

    k_zero<<<(NB*NQG*NP + 255) / 256, 256>>>();
    k_mlp<<<NTOK / 64, 256>>>(x, sw1, sb1, sw2, sb2, cw1, cb1, cw2, cb2);
    k_stats<<<NB, 256>>>(qs);
    k_accum<<<NB * 32, 64>>>(px, qs);
    k_finalize<<<NB, 64>>>();
    k_out<<<(NTOK * NP / 4) / 256, 256>>>(px, qs, out);
}

// round 3
// speedup vs baseline: 1.6466x; 1.6466x over previous
#include <cuda_runtime.h>
#include <cuda_bf16.h>
#include <cstdint>

#define NB   8
#define NS   2048
#define NH   256
#define NHH  128
#define NP   64
#define NQG  20
#define NTOK (NB*NS)

// ---- scratch (device globals; no allocation allowed) ----
__device__ float g_sim[NTOK];          // sim logits, then overwritten with exp(sim - M)
__device__ float g_conf[NTOK];         // sigmoid(conf logit)
__device__ float g_M[NB*NQG];
__device__ float g_Z[NB*NQG];
__device__ float g_cnt[NB*NQG];
__device__ float g_W[NB*NQG*NP];
__device__ float g_T[NB*NQG*NP];
__device__ float g_V[NB*NQG*NP];
__device__ __nv_bfloat16 g_Bh[256*256];  // weights [n=256][k=256], bf16 hi
__device__ __nv_bfloat16 g_Bl[256*256];  // bf16 lo residual

// ================= K_prep: transpose+split weights to bf16 hi/lo; zero accumulators =================
__global__ void k_prep(const float* __restrict__ sw1, const float* __restrict__ cw1) {
    int id = blockIdx.x * 256 + threadIdx.x;     // 32768
    int n = id & 127, k = id >> 7;               // k in [0,256)
    float vs = sw1[(size_t)k * NHH + n];
    float vc = cw1[(size_t)k * NHH + n];
    __nv_bfloat16 hs = __float2bfloat16_rn(vs);
    __nv_bfloat16 ls = __float2bfloat16_rn(vs - __bfloat162float(hs));
    __nv_bfloat16 hc = __float2bfloat16_rn(vc);
    __nv_bfloat16 lc = __float2bfloat16_rn(vc - __bfloat162float(hc));
    g_Bh[n * 256 + k] = hs;
    g_Bl[n * 256 + k] = ls;
    g_Bh[(128 + n) * 256 + k] = hc;
    g_Bl[(128 + n) * 256 + k] = lc;
    if (id < NB * NQG * NP) { g_W[id] = 0.f; g_T[id] = 0.f; }
}

// ================= K_mlp: mma.sync bf16 split-GEMM + fused layer-2 epilogue =================
#define MT 128
#define KC 64                 /* K chunk */
#define KST 72                /* smem row stride in halves (pad) */
// dynamic smem layout (in halves):
//   A_hi [128][72] : 0
//   A_lo [128][72] : 9216
//   B_hi [256][72] : 18432
//   B_lo [256][72] : 36864
#define SM_AH 0
#define SM_AL (128*KST)
#define SM_BH (2*128*KST)
#define SM_BL (2*128*KST + 256*KST)
#define MLP_SMEM ((2*128*KST + 2*256*KST) * 2)   /* 110592 bytes */

__device__ __forceinline__ void mma_bf16(float d[4], uint32_t a0, uint32_t a1,
                                         uint32_t a2, uint32_t a3,
                                         uint32_t b0, uint32_t b1) {
    asm volatile(
        "mma.sync.aligned.m16n8k16.row.col.f32.bf16.bf16.f32 "
        "{%0,%1,%2,%3}, {%4,%5,%6,%7}, {%8,%9}, {%0,%1,%2,%3};"
        : "+f"(d[0]), "+f"(d[1]), "+f"(d[2]), "+f"(d[3])
        : "r"(a0), "r"(a1), "r"(a2), "r"(a3), "r"(b0), "r"(b1));
}

__global__ __launch_bounds__(512, 1)
void k_mlp(const float* __restrict__ x,
           const float* __restrict__ sb1, const float* __restrict__ sb2,
           const float* __restrict__ cb1, const float* __restrict__ cb2,
           const float* __restrict__ sw2, const float* __restrict__ cw2)
{
    extern __shared__ __nv_bfloat16 sm[];
    __shared__ float b1s[256], w2s[256];
    __shared__ float part[128][4];

    const int tid  = threadIdx.x;
    const int wid  = tid >> 5;
    const int lane = tid & 31;
    const int gid  = lane >> 2;     // group id 0..7
    const int tig  = lane & 3;      // thread in group
    const int mw   = wid & 3;       // m-warp: rows mw*32 .. +31
    const int nw   = wid >> 2;      // n-warp: cols nw*64 .. +63
    const int m0w  = mw * 32;
    const int n0w  = nw * 64;
    const int row0 = blockIdx.x * MT;

    if (tid < 256) {
        b1s[tid] = (tid < 128) ? sb1[tid] : cb1[tid - 128];
        w2s[tid] = (tid < 128) ? sw2[tid] : cw2[tid - 128];
    }

    float d[2][8][4];
    #pragma unroll
    for (int mi = 0; mi < 2; ++mi)
        #pragma unroll
        for (int ni = 0; ni < 8; ++ni)
            #pragma unroll
            for (int j = 0; j < 4; ++j) d[mi][ni][j] = 0.f;

    for (int c = 0; c < NH / KC; ++c) {
        const int kb = c * KC;
        // ---- fill A: 128 rows x 64 k fp32 -> bf16 hi/lo ----
        #pragma unroll
        for (int i = 0; i < 4; ++i) {
            int idx = tid * 4 + i;              // f4 index 0..2047
            int row = idx >> 4, k = (idx & 15) * 4;
            float4 v = *(const float4*)&x[(size_t)(row0 + row) * NH + kb + k];
            __nv_bfloat16 h0 = __float2bfloat16_rn(v.x), h1 = __float2bfloat16_rn(v.y);
            __nv_bfloat16 h2 = __float2bfloat16_rn(v.z), h3 = __float2bfloat16_rn(v.w);
            __nv_bfloat162 hA = {h0, h1}, hB = {h2, h3};
            __nv_bfloat162 lA = {__float2bfloat16_rn(v.x - __bfloat162float(h0)),
                                 __float2bfloat16_rn(v.y - __bfloat162float(h1))};
            __nv_bfloat162 lB = {__float2bfloat16_rn(v.z - __bfloat162float(h2)),
                                 __float2bfloat16_rn(v.w - __bfloat162float(h3))};
            uint2 hw = {*(uint32_t*)&hA, *(uint32_t*)&hB};
            uint2 lw = {*(uint32_t*)&lA, *(uint32_t*)&lB};
            *(uint2*)&sm[SM_AH + row * KST + k] = hw;
            *(uint2*)&sm[SM_AL + row * KST + k] = lw;
        }
        // ---- fill B: 256 n x 64 k bf16 hi & lo (pre-split) ----
        #pragma unroll
        for (int i = 0; i < 4; ++i) {
            int idx = tid * 4 + i;              // u4 index 0..2047 (8 halves each)
            int n = idx >> 3, k = (idx & 7) * 8;
            *(uint4*)&sm[SM_BH + n * KST + k] = *(const uint4*)&g_Bh[n * 256 + kb + k];
            *(uint4*)&sm[SM_BL + n * KST + k] = *(const uint4*)&g_Bl[n * 256 + kb + k];
        }
        __syncthreads();

        #pragma unroll
        for (int ks = 0; ks < KC / 16; ++ks) {
            const int kk = ks * 16;
            uint32_t ah[2][4], al[2][4];
            #pragma unroll
            for (int mi = 0; mi < 2; ++mi) {
                int off = (m0w + mi * 16 + gid) * KST + kk + 2 * tig;
                ah[mi][0] = *(const uint32_t*)&sm[SM_AH + off];
                ah[mi][1] = *(const uint32_t*)&sm[SM_AH + off + 8 * KST];
                ah[mi][2] = *(const uint32_t*)&sm[SM_AH + off + 8];
                ah[mi][3] = *(const uint32_t*)&sm[SM_AH + off + 8 * KST + 8];
                al[mi][0] = *(const uint32_t*)&sm[SM_AL + off];
                al[mi][1] = *(const uint32_t*)&sm[SM_AL + off + 8 * KST];
                al[mi][2] = *(const uint32_t*)&sm[SM_AL + off + 8];
                al[mi][3] = *(const uint32_t*)&sm[SM_AL + off + 8 * KST + 8];
            }
            #pragma unroll
            for (int ni = 0; ni < 8; ++ni) {
                int offb = (n0w + ni * 8 + gid) * KST + kk + 2 * tig;
                uint32_t b0 = *(const uint32_t*)&sm[SM_BH + offb];
                uint32_t b1 = *(const uint32_t*)&sm[SM_BH + offb + 8];
                #pragma unroll
                for (int mi = 0; mi < 2; ++mi) {
                    mma_bf16(d[mi][ni], ah[mi][0], ah[mi][1], ah[mi][2], ah[mi][3], b0, b1);
                    mma_bf16(d[mi][ni], al[mi][0], al[mi][1], al[mi][2], al[mi][3], b0, b1);
                }
            }
            #pragma unroll
            for (int ni = 0; ni < 8; ++ni) {
                int offb = (n0w + ni * 8 + gid) * KST + kk + 2 * tig;
                uint32_t b0 = *(const uint32_t*)&sm[SM_BL + offb];
                uint32_t b1 = *(const uint32_t*)&sm[SM_BL + offb + 8];
                #pragma unroll
                for (int mi = 0; mi < 2; ++mi)
                    mma_bf16(d[mi][ni], ah[mi][0], ah[mi][1], ah[mi][2], ah[mi][3], b0, b1);
            }
        }
        __syncthreads();
    }

    // ---- epilogue: bias + relu + w2-dot over this warp's 64 cols ----
    float p[2][2];
    #pragma unroll
    for (int mi = 0; mi < 2; ++mi) {
        p[mi][0] = 0.f; p[mi][1] = 0.f;
        #pragma unroll
        for (int ni = 0; ni < 8; ++ni) {
            int cb = n0w + ni * 8 + 2 * tig;
            #pragma unroll
            for (int j = 0; j < 2; ++j) {
                float h0 = fmaxf(d[mi][ni][j]     + b1s[cb + j], 0.f);
                float h1 = fmaxf(d[mi][ni][2 + j] + b1s[cb + j], 0.f);
                p[mi][0] = fmaf(h0, w2s[cb + j], p[mi][0]);
                p[mi][1] = fmaf(h1, w2s[cb + j], p[mi][1]);
            }
        }
    }
    #pragma unroll
    for (int off = 1; off <= 2; off <<= 1) {
        #pragma unroll
        for (int mi = 0; mi < 2; ++mi) {
            p[mi][0] += __shfl_xor_sync(0xffffffffu, p[mi][0], off);
            p[mi][1] += __shfl_xor_sync(0xffffffffu, p[mi][1], off);
        }
    }
    if (tig == 0) {
        #pragma unroll
        for (int mi = 0; mi < 2; ++mi) {
            part[m0w + mi * 16 + gid][nw]     = p[mi][0];
            part[m0w + mi * 16 + gid + 8][nw] = p[mi][1];
        }
    }
    __syncthreads();
    if (tid < 128) {
        float sv = part[tid][0] + part[tid][1] + sb2[0];
        float cl = part[tid][2] + part[tid][3] + cb2[0];
        g_sim[row0 + tid]  = sv;
        g_conf[row0 + tid] = 1.f / (1.f + __expf(-cl));
    }
}

// ================= K2: per-(batch,group) max / Z / count; write e = exp(sim-M) =================
__global__ void k_stats(const int* __restrict__ questions) {
    const int b = blockIdx.x;
    const int tid = threadIdx.x;          // 256
    __shared__ unsigned menc[NQG];
    __shared__ float Msh[NQG], Zsh[NQG];
    __shared__ int   csh[NQG];
    if (tid < NQG) { menc[tid] = 0u; Zsh[tid] = 0.f; csh[tid] = 0; }
    __syncthreads();
    const int base = b * NS;
    for (int s = tid; s < NS; s += 256) {
        float v = g_sim[base + s];
        unsigned bits = __float_as_uint(v);
        unsigned enc = (bits & 0x80000000u) ? ~bits : (bits | 0x80000000u);
        atomicMax(&menc[questions[base + s]], enc);
    }
    __syncthreads();
    if (tid < NQG) {
        unsigned e = menc[tid];
        float gm = -3.4e38f;
        if (e) gm = (e & 0x80000000u) ? __uint_as_float(e & 0x7fffffffu)
                                      : __uint_as_float(~e);
        float M = fmaxf(gm, 0.f);
        Msh[tid] = M;
        g_M[b * NQG + tid] = M;
    }
    __syncthreads();
    for (int s = tid; s < NS; s += 256) {
        int q = questions[base + s];
        float e = __expf(g_sim[base + s] - Msh[q]);
        g_sim[base + s] = e;
        atomicAdd(&Zsh[q], e);
        atomicAdd(&csh[q], 1);
    }
    __syncthreads();
    if (tid < NQG) {
        g_Z[b * NQG + tid]   = Zsh[tid];
        g_cnt[b * NQG + tid] = (float)csh[tid];
    }
}

// ================= K3: per-group weighted sums of param_x (256 thr, 128-token chunks) =================
__global__ __launch_bounds__(256) void k_accum(const float* __restrict__ px,
                                               const int* __restrict__ qs) {
    const int b = blockIdx.x >> 4;
    const int chunk = blockIdx.x & 15;
    const int t0 = b * NS + chunk * 128;
    const int p = threadIdx.x & 63;
    const int u = threadIdx.x >> 6;
    __shared__ float accW[4][NQG][NP];
    __shared__ float accT[4][NQG][NP];
    __shared__ float esh[128];
    __shared__ int   qsh[128];
    #pragma unroll
    for (int g = 0; g < NQG; ++g) { accW[u][g][p] = 0.f; accT[u][g][p] = 0.f; }
    if (threadIdx.x < 128) {
        esh[threadIdx.x] = g_sim[t0 + threadIdx.x];
        qsh[threadIdx.x] = qs[t0 + threadIdx.x];
    }
    __syncthreads();
    const int tb = u * 32;
    for (int c = 0; c < 32; c += 8) {
        float pxv[8];
        #pragma unroll
        for (int k = 0; k < 8; ++k)
            pxv[k] = px[(size_t)(t0 + tb + c + k) * NP + p];
        #pragma unroll
        for (int k = 0; k < 8; ++k) {
            int g = qsh[tb + c + k];
            accW[u][g][p] = fmaf(esh[tb + c + k], pxv[k], accW[u][g][p]);
            accT[u][g][p] += pxv[k];
        }
    }
    __syncthreads();
    const int bg = b * NQG;
    for (int i = threadIdx.x; i < NQG * NP; i += 256) {
        int g = i >> 6, pp = i & 63;
        float w = accW[0][g][pp] + accW[1][g][pp] + accW[2][g][pp] + accW[3][g][pp];
        float t = accT[0][g][pp] + accT[1][g][pp] + accT[2][g][pp] + accT[3][g][pp];
        atomicAdd(&g_W[(bg + g) * NP + pp], w);
        atomicAdd(&g_T[(bg + g) * NP + pp], t);
    }
}

// ================= K4: finalize V_g =================
__global__ void k_finalize() {
    const int b = blockIdx.x;
    const int p = threadIdx.x;   // 64
    const int bg = b * NQG;
    float tall = 0.f;
    for (int g = 0; g < NQG; ++g) tall += g_T[(bg + g) * NP + p];
    for (int g = 0; g < NQG; ++g) {
        float M  = g_M[bg + g];
        float em = __expf(-M);
        float Tg = g_T[(bg + g) * NP + p];
        float Z  = g_Z[bg + g] + ((float)NS - g_cnt[bg + g]) * em;
        g_V[(bg + g) * NP + p] = (g_W[(bg + g) * NP + p] + em * (tall - Tg)) / Z;
    }
}

// ================= K5: output blend =================
__global__ void k_out(const float* __restrict__ px, const int* __restrict__ questions,
                      float* __restrict__ out) {
    int fid = blockIdx.x * blockDim.x + threadIdx.x;
    int t  = fid >> 4;
    int pq = fid & 15;
    int b  = t >> 11;
    int q  = questions[t];
    float c = g_conf[t];
    float4 pv = *(const float4*)&px[(size_t)t * NP + pq * 4];
    float4 vv = *(const float4*)&g_V[((b * NQG) + q) * NP + pq * 4];
    float4 o;
    float ic = 1.f - c;
    o.x = fmaf(c, pv.x, ic * vv.x);
    o.y = fmaf(c, pv.y, ic * vv.y);
    o.z = fmaf(c, pv.z, ic * vv.z);
    o.w = fmaf(c, pv.w, ic * vv.w);
    *(float4*)&out[(size_t)t * NP + pq * 4] = o;
}

extern "C" void kernel_launch(void* const* d_in, const int* in_sizes, int n_in,
                              void* d_out, int out_size) {
    const float* x   = (const float*)d_in[0];
    const float* px  = (const float*)d_in[1];
    const float* sw1 = (const float*)d_in[2];
    const float* sb1 = (const float*)d_in[3];
    const float* sw2 = (const float*)d_in[4];
    const float* sb2 = (const float*)d_in[5];
    const float* cw1 = (const float*)d_in[6];
    const float* cb1 = (const float*)d_in[7];
    const float* cw2 = (const float*)d_in[8];
    const float* cb2 = (const float*)d_in[9];
    const int*   qs  = (const int*)d_in[10];
    float* out = (float*)d_out;

    cudaFuncSetAttribute(k_mlp, cudaFuncAttributeMaxDynamicSharedMemorySize, MLP_SMEM);

    k_prep<<<128, 256>>>(sw1, cw1);
    k_mlp<<<NTOK / MT, 512, MLP_SMEM>>>(x, sb1, sb2, cb1, cb2, sw2, cw2);
    k_stats<<<NB, 256>>>(qs);
    k_accum<<<NB * 16, 256>>>(px, qs);
    k_finalize<<<NB, 64>>>();
    k_out<<<(NTOK * NP / 4) / 256, 256>>>(px, qs, out);
}

// round 4
// speedup vs baseline: 2.2417x; 1.3614x over previous
#include <cuda_runtime.h>
#include <cuda_bf16.h>
#include <cstdint>

#define NB   8
#define NS   2048
#define NH   256
#define NHH  128
#define NP   64
#define NQG  20
#define NTOK (NB*NS)

// ---- scratch (device globals; no allocation allowed) ----
__device__ float g_sim[NTOK];            // sim logits
__device__ float g_conf[NTOK];           // sigmoid(conf logit)
__device__ unsigned g_menc[NB*NQG];      // encoded per-group max
__device__ float g_Z[NB*NQG];
__device__ float g_cnt[NB*NQG];
__device__ float g_W[NB*NQG*NP];
__device__ float g_T[NB*NQG*NP];
__device__ __nv_bfloat16 g_Bh[256*256];  // weights [n=256][k=256], bf16 hi
__device__ __nv_bfloat16 g_Bl[256*256];  // bf16 lo residual

__device__ __forceinline__ uint32_t smem_u32(const void* p) {
    uint32_t a;
    asm("{ .reg .u64 t; cvta.to.shared.u64 t, %1; cvt.u32.u64 %0, t; }" : "=r"(a) : "l"(p));
    return a;
}
#define CP_ASYNC16(smaddr, gptr) \
    asm volatile("cp.async.cg.shared.global [%0], [%1], 16;" :: "r"(smaddr), "l"(gptr))
#define CP_COMMIT() asm volatile("cp.async.commit_group;" ::: "memory")
#define CP_WAIT1()  asm volatile("cp.async.wait_group 1;" ::: "memory")
#define CP_WAIT0()  asm volatile("cp.async.wait_group 0;" ::: "memory")

__device__ __forceinline__ float dec_menc(unsigned e) {
    if (e == 0u) return -3.4e38f;
    return (e & 0x80000000u) ? __uint_as_float(e & 0x7fffffffu) : __uint_as_float(~e);
}

// ================= K_prep: transpose+split weights to bf16 hi/lo; zero accumulators =================
__global__ void k_prep(const float* __restrict__ sw1, const float* __restrict__ cw1) {
    int id = blockIdx.x * 256 + threadIdx.x;     // 32768
    int n = id >> 8, k = id & 255;               // n in [0,128), k in [0,256)
    float vs = sw1[(size_t)k * NHH + n];
    float vc = cw1[(size_t)k * NHH + n];
    __nv_bfloat16 hs = __float2bfloat16_rn(vs);
    __nv_bfloat16 ls = __float2bfloat16_rn(vs - __bfloat162float(hs));
    __nv_bfloat16 hc = __float2bfloat16_rn(vc);
    __nv_bfloat16 lc = __float2bfloat16_rn(vc - __bfloat162float(hc));
    g_Bh[n * 256 + k] = hs;
    g_Bl[n * 256 + k] = ls;
    g_Bh[(128 + n) * 256 + k] = hc;
    g_Bl[(128 + n) * 256 + k] = lc;
    if (id < NB * NQG * NP) { g_W[id] = 0.f; g_T[id] = 0.f; }
    if (id < NB * NQG) { g_menc[id] = 0u; g_Z[id] = 0.f; g_cnt[id] = 0.f; }
}

// ================= K_mlp: pipelined mma.sync bf16 split-GEMM + fused epilogue =================
#define MT 128
#define KC 64
#define NCHUNK (NH/KC)
#define KST 72
// half-index layout in dynamic smem:
#define SM_AH 0
#define SM_AL (128*KST)                 /* 9216  */
#define SM_B0 (2*128*KST)               /* 18432 */
#define BBUF  (2*256*KST)               /* 36864 halves per buffer (hi+lo) */
#define BLOFF (256*KST)                 /* 18432 */
#define MLP_SMEM ((SM_B0 + 2*BBUF) * 2) /* 184320 bytes */

__device__ __forceinline__ void mma_bf16(float d[4], uint32_t a0, uint32_t a1,
                                         uint32_t a2, uint32_t a3,
                                         uint32_t b0, uint32_t b1) {
    asm volatile(
        "mma.sync.aligned.m16n8k16.row.col.f32.bf16.bf16.f32 "
        "{%0,%1,%2,%3}, {%4,%5,%6,%7}, {%8,%9}, {%0,%1,%2,%3};"
        : "+f"(d[0]), "+f"(d[1]), "+f"(d[2]), "+f"(d[3])
        : "r"(a0), "r"(a1), "r"(a2), "r"(a3), "r"(b0), "r"(b1));
}

__global__ __launch_bounds__(512, 1)
void k_mlp(const float* __restrict__ x,
           const float* __restrict__ sb1, const float* __restrict__ sb2,
           const float* __restrict__ cb1, const float* __restrict__ cb2,
           const float* __restrict__ sw2, const float* __restrict__ cw2,
           const int* __restrict__ qs)
{
    extern __shared__ __nv_bfloat16 sm[];
    __shared__ float b1s[256], w2s[256];
    __shared__ float part[128][4];

    const int tid  = threadIdx.x;
    const int wid  = tid >> 5;
    const int lane = tid & 31;
    const int gid  = lane >> 2;
    const int tig  = lane & 3;
    const int mw   = wid & 3;
    const int nw   = wid >> 2;
    const int m0w  = mw * 32;
    const int n0w  = nw * 64;
    const int row0 = blockIdx.x * MT;
    const uint32_t smb = smem_u32(sm);

    if (tid < 256) {
        b1s[tid] = (tid < 128) ? sb1[tid] : cb1[tid - 128];
        w2s[tid] = (tid < 128) ? sw2[tid] : cw2[tid - 128];
    }

    float d[2][8][4];
    #pragma unroll
    for (int mi = 0; mi < 2; ++mi)
        #pragma unroll
        for (int ni = 0; ni < 8; ++ni)
            #pragma unroll
            for (int j = 0; j < 4; ++j) d[mi][ni][j] = 0.f;

    // B fill indices (per thread: 4 hi + 4 lo 16B copies)
    const int bfn = (tid * 4) >> 3;            // n row for i=0 (increments by /8)
    // A fill indices
    const int arow = (tid * 4) >> 4;           // token row (4 f4 per row group)

    // ---- issue B chunk 0 (cp.async) ----
    #pragma unroll
    for (int i = 0; i < 4; ++i) {
        int idx = tid * 4 + i;
        int n = idx >> 3, k = (idx & 7) * 8;
        uint32_t dh = smb + 2 * (SM_B0 + n * KST + k);
        CP_ASYNC16(dh, &g_Bh[n * 256 + k]);
        CP_ASYNC16(dh + 2 * BLOFF, &g_Bl[n * 256 + k]);
    }
    CP_COMMIT();

    // ---- load A chunk 0 into regs ----
    float4 av[4];
    {
        const float* xr = &x[(size_t)(row0 + arow) * NH];
        #pragma unroll
        for (int i = 0; i < 4; ++i) {
            int idx = tid * 4 + i;
            av[i] = *(const float4*)&xr[((idx & 15) - ((tid * 4) & 15)) * 0 + (idx & 15) * 4
                                        + ((idx >> 4) - arow) * NH];
        }
    }

    for (int c = 0; c < NCHUNK; ++c) {
        const int buf = c & 1;
        // issue B chunk c+1 into other buffer
        if (c < NCHUNK - 1) {
            const int kb = (c + 1) * KC;
            #pragma unroll
            for (int i = 0; i < 4; ++i) {
                int idx = tid * 4 + i;
                int n = idx >> 3, k = (idx & 7) * 8;
                uint32_t dh = smb + 2 * (SM_B0 + (buf ^ 1) * BBUF + n * KST + k);
                CP_ASYNC16(dh, &g_Bh[n * 256 + kb + k]);
                CP_ASYNC16(dh + 2 * BLOFF, &g_Bl[n * 256 + kb + k]);
            }
            CP_COMMIT();
        }
        // convert + store A regs (chunk c) to smem
        #pragma unroll
        for (int i = 0; i < 4; ++i) {
            int idx = tid * 4 + i;
            int row = idx >> 4, k = (idx & 15) * 4;
            float4 v = av[i];
            __nv_bfloat16 h0 = __float2bfloat16_rn(v.x), h1 = __float2bfloat16_rn(v.y);
            __nv_bfloat16 h2 = __float2bfloat16_rn(v.z), h3 = __float2bfloat16_rn(v.w);
            __nv_bfloat162 hA = {h0, h1}, hB = {h2, h3};
            __nv_bfloat162 lA = {__float2bfloat16_rn(v.x - __bfloat162float(h0)),
                                 __float2bfloat16_rn(v.y - __bfloat162float(h1))};
            __nv_bfloat162 lB = {__float2bfloat16_rn(v.z - __bfloat162float(h2)),
                                 __float2bfloat16_rn(v.w - __bfloat162float(h3))};
            uint2 hw = {*(uint32_t*)&hA, *(uint32_t*)&hB};
            uint2 lw = {*(uint32_t*)&lA, *(uint32_t*)&lB};
            *(uint2*)&sm[SM_AH + row * KST + k] = hw;
            *(uint2*)&sm[SM_AL + row * KST + k] = lw;
        }
        // issue A LDGs for chunk c+1 (in flight during MMA)
        if (c < NCHUNK - 1) {
            const int kb = (c + 1) * KC;
            #pragma unroll
            for (int i = 0; i < 4; ++i) {
                int idx = tid * 4 + i;
                int row = idx >> 4, k = (idx & 15) * 4;
                av[i] = *(const float4*)&x[(size_t)(row0 + row) * NH + kb + k];
            }
        }
        if (c < NCHUNK - 1) { CP_WAIT1(); } else { CP_WAIT0(); }
        __syncthreads();

        const int B0 = SM_B0 + buf * BBUF;
        #pragma unroll
        for (int ks = 0; ks < KC / 16; ++ks) {
            const int kk = ks * 16;
            uint32_t ah[2][4], al[2][4];
            #pragma unroll
            for (int mi = 0; mi < 2; ++mi) {
                int off = (m0w + mi * 16 + gid) * KST + kk + 2 * tig;
                ah[mi][0] = *(const uint32_t*)&sm[SM_AH + off];
                ah[mi][1] = *(const uint32_t*)&sm[SM_AH + off + 8 * KST];
                ah[mi][2] = *(const uint32_t*)&sm[SM_AH + off + 8];
                ah[mi][3] = *(const uint32_t*)&sm[SM_AH + off + 8 * KST + 8];
                al[mi][0] = *(const uint32_t*)&sm[SM_AL + off];
                al[mi][1] = *(const uint32_t*)&sm[SM_AL + off + 8 * KST];
                al[mi][2] = *(const uint32_t*)&sm[SM_AL + off + 8];
                al[mi][3] = *(const uint32_t*)&sm[SM_AL + off + 8 * KST + 8];
            }
            #pragma unroll
            for (int ni = 0; ni < 8; ++ni) {
                int offb = B0 + (n0w + ni * 8 + gid) * KST + kk + 2 * tig;
                uint32_t b0 = *(const uint32_t*)&sm[offb];
                uint32_t b1 = *(const uint32_t*)&sm[offb + 8];
                #pragma unroll
                for (int mi = 0; mi < 2; ++mi) {
                    mma_bf16(d[mi][ni], ah[mi][0], ah[mi][1], ah[mi][2], ah[mi][3], b0, b1);
                    mma_bf16(d[mi][ni], al[mi][0], al[mi][1], al[mi][2], al[mi][3], b0, b1);
                }
            }
            #pragma unroll
            for (int ni = 0; ni < 8; ++ni) {
                int offb = B0 + BLOFF + (n0w + ni * 8 + gid) * KST + kk + 2 * tig;
                uint32_t b0 = *(const uint32_t*)&sm[offb];
                uint32_t b1 = *(const uint32_t*)&sm[offb + 8];
                #pragma unroll
                for (int mi = 0; mi < 2; ++mi)
                    mma_bf16(d[mi][ni], ah[mi][0], ah[mi][1], ah[mi][2], ah[mi][3], b0, b1);
            }
        }
        __syncthreads();
    }

    // ---- epilogue: bias + relu + w2-dot; fused group-max atomics ----
    float p[2][2];
    #pragma unroll
    for (int mi = 0; mi < 2; ++mi) {
        p[mi][0] = 0.f; p[mi][1] = 0.f;
        #pragma unroll
        for (int ni = 0; ni < 8; ++ni) {
            int cb = n0w + ni * 8 + 2 * tig;
            #pragma unroll
            for (int j = 0; j < 2; ++j) {
                float h0 = fmaxf(d[mi][ni][j]     + b1s[cb + j], 0.f);
                float h1 = fmaxf(d[mi][ni][2 + j] + b1s[cb + j], 0.f);
                p[mi][0] = fmaf(h0, w2s[cb + j], p[mi][0]);
                p[mi][1] = fmaf(h1, w2s[cb + j], p[mi][1]);
            }
        }
    }
    #pragma unroll
    for (int off = 1; off <= 2; off <<= 1) {
        #pragma unroll
        for (int mi = 0; mi < 2; ++mi) {
            p[mi][0] += __shfl_xor_sync(0xffffffffu, p[mi][0], off);
            p[mi][1] += __shfl_xor_sync(0xffffffffu, p[mi][1], off);
        }
    }
    if (tig == 0) {
        #pragma unroll
        for (int mi = 0; mi < 2; ++mi) {
            part[m0w + mi * 16 + gid][nw]     = p[mi][0];
            part[m0w + mi * 16 + gid + 8][nw] = p[mi][1];
        }
    }
    __syncthreads();
    if (tid < 128) {
        int row = row0 + tid;
        float sv = part[tid][0] + part[tid][1] + sb2[0];
        float cl = part[tid][2] + part[tid][3] + cb2[0];
        g_sim[row]  = sv;
        g_conf[row] = 1.f / (1.f + __expf(-cl));
        unsigned bits = __float_as_uint(sv);
        unsigned enc = (bits & 0x80000000u) ? ~bits : (bits | 0x80000000u);
        int b = row >> 11;
        atomicMax(&g_menc[b * NQG + qs[row]], enc);
    }
}

// ================= K_accum: exp/Z/count + per-group weighted sums =================
__global__ __launch_bounds__(256) void k_accum(const float* __restrict__ px,
                                               const int* __restrict__ qs) {
    const int b = blockIdx.x >> 5;
    const int chunk = blockIdx.x & 31;
    const int t0 = b * NS + chunk * 64;
    const int p = threadIdx.x & 63;
    const int u = threadIdx.x >> 6;
    __shared__ float accW[4][NQG][NP];
    __shared__ float accT[4][NQG][NP];
    __shared__ float esh[64];
    __shared__ int   qsh[64];
    __shared__ float Msh[NQG], Zsh[NQG];
    __shared__ int   csh[NQG];
    if (threadIdx.x < NQG) {
        Msh[threadIdx.x] = fmaxf(dec_menc(g_menc[b * NQG + threadIdx.x]), 0.f);
        Zsh[threadIdx.x] = 0.f; csh[threadIdx.x] = 0;
    }
    #pragma unroll
    for (int g = 0; g < NQG; ++g) { accW[u][g][p] = 0.f; accT[u][g][p] = 0.f; }
    __syncthreads();
    if (threadIdx.x < 64) {
        int q = qs[t0 + threadIdx.x];
        qsh[threadIdx.x] = q;
        float e = __expf(g_sim[t0 + threadIdx.x] - Msh[q]);
        esh[threadIdx.x] = e;
        atomicAdd(&Zsh[q], e);
        atomicAdd(&csh[q], 1);
    }
    __syncthreads();
    const int tb = u * 16;
    float pxv[16];
    const float* base = px + (size_t)(t0 + tb) * NP + p;
    #pragma unroll
    for (int k = 0; k < 16; ++k) pxv[k] = base[(size_t)k * NP];
    #pragma unroll
    for (int k = 0; k < 16; ++k) {
        int g = qsh[tb + k];
        accW[u][g][p] = fmaf(esh[tb + k], pxv[k], accW[u][g][p]);
        accT[u][g][p] += pxv[k];
    }
    __syncthreads();
    const int bg = b * NQG;
    for (int i = threadIdx.x; i < NQG * NP; i += 256) {
        int g = i >> 6, pp = i & 63;
        float w = accW[0][g][pp] + accW[1][g][pp] + accW[2][g][pp] + accW[3][g][pp];
        float t = accT[0][g][pp] + accT[1][g][pp] + accT[2][g][pp] + accT[3][g][pp];
        atomicAdd(&g_W[(bg + g) * NP + pp], w);
        atomicAdd(&g_T[(bg + g) * NP + pp], t);
    }
    if (threadIdx.x < NQG) {
        atomicAdd(&g_Z[bg + threadIdx.x], Zsh[threadIdx.x]);
        atomicAdd(&g_cnt[bg + threadIdx.x], (float)csh[threadIdx.x]);
    }
}

// ================= K_out: finalize V (recomputed per block) + blend =================
__global__ __launch_bounds__(256) void k_out(const float* __restrict__ px,
                                             const int* __restrict__ qs,
                                             float* __restrict__ out) {
    const int b = blockIdx.x >> 4;
    const int chunk = blockIdx.x & 15;
    const int t0 = b * NS + chunk * 128;
    const int tid = threadIdx.x;
    const int bg = b * NQG;
    __shared__ float V[NQG][NP];
    __shared__ float tallp[NP];
    __shared__ float Msh[NQG], Zs[NQG], cs[NQG];
    __shared__ float csh2[128];
    __shared__ int   qsh2[128];
    if (tid < NQG) {
        Msh[tid] = fmaxf(dec_menc(g_menc[bg + tid]), 0.f);
        Zs[tid] = g_Z[bg + tid];
        cs[tid] = g_cnt[bg + tid];
    }
    if (tid < NP) {
        float t = 0.f;
        #pragma unroll
        for (int g = 0; g < NQG; ++g) t += g_T[(bg + g) * NP + tid];
        tallp[tid] = t;
    }
    if (tid < 128) { csh2[tid] = g_conf[t0 + tid]; qsh2[tid] = qs[t0 + tid]; }
    __syncthreads();
    for (int i = tid; i < NQG * NP; i += 256) {
        int g = i >> 6, p = i & 63;
        float em = __expf(-Msh[g]);
        float Z  = Zs[g] + ((float)NS - cs[g]) * em;
        V[g][p] = (g_W[(bg + g) * NP + p] + em * (tallp[p] - g_T[(bg + g) * NP + p])) / Z;
    }
    __syncthreads();
    #pragma unroll
    for (int i = tid; i < 128 * 16; i += 256) {
        int t = i >> 4, pq = i & 15;
        int tok = t0 + t;
        float c = csh2[t];
        int q = qsh2[t];
        float4 pv = *(const float4*)&px[(size_t)tok * NP + pq * 4];
        float4 vv = *(const float4*)&V[q][pq * 4];
        float ic = 1.f - c;
        float4 o;
        o.x = fmaf(c, pv.x, ic * vv.x);
        o.y = fmaf(c, pv.y, ic * vv.y);
        o.z = fmaf(c, pv.z, ic * vv.z);
        o.w = fmaf(c, pv.w, ic * vv.w);
        *(float4*)&out[(size_t)tok * NP + pq * 4] = o;
    }
}

extern "C" void kernel_launch(void* const* d_in, const int* in_sizes, int n_in,
                              void* d_out, int out_size) {
    const float* x   = (const float*)d_in[0];
    const float* px  = (const float*)d_in[1];
    const float* sw1 = (const float*)d_in[2];
    const float* sb1 = (const float*)d_in[3];
    const float* sw2 = (const float*)d_in[4];
    const float* sb2 = (const float*)d_in[5];
    const float* cw1 = (const float*)d_in[6];
    const float* cb1 = (const float*)d_in[7];
    const float* cw2 = (const float*)d_in[8];
    const float* cb2 = (const float*)d_in[9];
    const int*   qs  = (const int*)d_in[10];
    float* out = (float*)d_out;

    cudaFuncSetAttribute(k_mlp, cudaFuncAttributeMaxDynamicSharedMemorySize, MLP_SMEM);

    k_prep<<<128, 256>>>(sw1, cw1);
    k_mlp<<<NTOK / MT, 512, MLP_SMEM>>>(x, sb1, sb2, cb1, cb2, sw2, cw2, qs);
    k_accum<<<NB * 32, 256>>>(px, qs);
    k_out<<<NB * 16, 256>>>(px, qs, out);
}